// round 15
// baseline (speedup 1.0000x reference)
#include <cuda_runtime.h>
#include <cuda_fp16.h>
#include <cstdint>

#define Nn 20000
#define Fc 64
#define Zs 10
#define Ee 320000

// ---- scratch (device globals; no allocation) ----
__device__ uint2  d_uph[Nn * Fc];      // fp16-packed (s,v0|v1,v2), inv folded
__device__ float4 d_skip[Nn * Fc];     // packed skip, inv folded
__device__ float4 d_acc[Nn * Fc];      // message accumulator
__device__ float  d_wsc[Zs * Fc * 12]; // Wsc projected, contiguous: [(z*64+u)*12+b]
__device__ int    d_cum[Zs + 1];

constexpr float INV  = 0.125f;  // 1/sqrt(64)
constexpr float EPSC = 0.25f;

typedef unsigned long long ull;

__device__ __forceinline__ float silu(float x) {
    return __fdividef(x, 1.0f + __expf(-x));
}
__device__ __forceinline__ ull pk2(float a, float b) {
    ull r; asm("mov.b64 %0, {%1, %2};" : "=l"(r) : "f"(a), "f"(b)); return r;
}
__device__ __forceinline__ void upk2(ull v, float& a, float& b) {
    asm("mov.b64 {%0, %1}, %2;" : "=f"(a), "=f"(b) : "l"(v));
}
__device__ __forceinline__ void fma2p(ull& d, ull a, ull b) {
    asm("fma.rn.f32x2 %0, %1, %2, %0;" : "+l"(d) : "l"(a), "l"(b));
}
__device__ __forceinline__ void red4(float* p, float a, float b, float c, float d) {
    ull gp = (ull)__cvta_generic_to_global(p);
    asm volatile("red.global.add.v4.f32 [%0], {%1, %2, %3, %4};"
                 :: "l"(gp), "f"(a), "f"(b), "f"(c), "f"(d) : "memory");
}
__device__ __forceinline__ uint32_t smem_u32(const void* p) {
    uint32_t a;
    asm("{ .reg .u64 t; cvta.to.shared.u64 t, %1; cvt.u32.u64 %0, t; }"
        : "=r"(a) : "l"(p));
    return a;
}
#define SWZ128(b) ((b) ^ (((b) >> 3) & 0x70))

__device__ __forceinline__ uint32_t pkhf(float a, float b) {
    __half2 t = __floats2half2_rn(a, b);
    return *(uint32_t*)&t;
}
__device__ __forceinline__ float2 uphf(uint32_t v) {
    return __half22float2(*(__half2*)&v);
}

// ---- warp-level mma.sync helpers (fp16 in, fp32 accum) ----
__device__ __forceinline__ void ldsmA(uint32_t base, int mr, int k0, int lane, uint32_t a[4]) {
    int row = mr + (lane & 7) + ((lane >> 3) & 1) * 8;
    int col = k0 + (lane >> 4) * 8;
    uint32_t off = (uint32_t)(row * 128 + col * 2);
    uint32_t addr = base + SWZ128(off);
    asm volatile("ldmatrix.sync.aligned.m8n8.x4.shared.b16 {%0,%1,%2,%3}, [%4];"
        : "=r"(a[0]), "=r"(a[1]), "=r"(a[2]), "=r"(a[3]) : "r"(addr));
}
__device__ __forceinline__ void ldsmB(uint32_t base, int k0, int n0, int lane, uint32_t b[2]) {
    int k = k0 + (lane & 15);
    uint32_t off = (uint32_t)(k * 128 + n0 * 2);
    uint32_t addr = base + SWZ128(off);
    asm volatile("ldmatrix.sync.aligned.m8n8.x2.trans.shared.b16 {%0,%1}, [%2];"
        : "=r"(b[0]), "=r"(b[1]) : "r"(addr));
}
__device__ __forceinline__ void mma16816(float c[4], const uint32_t a[4], const uint32_t b[2]) {
    asm volatile("mma.sync.aligned.m16n8k16.row.col.f32.f16.f16.f32 "
        "{%0,%1,%2,%3}, {%4,%5,%6,%7}, {%8,%9}, {%0,%1,%2,%3};"
        : "+f"(c[0]), "+f"(c[1]), "+f"(c[2]), "+f"(c[3])
        : "r"(a[0]), "r"(a[1]), "r"(a[2]), "r"(a[3]), "r"(b[0]), "r"(b[1]));
}

// ---- k0: species prefix + Wsc @ Proj (contiguous padded-12 layout) ----
__global__ void k0(const int* __restrict__ counts,
                   const float* __restrict__ Wsc,
                   const float* __restrict__ Proj) {
    int tid = threadIdx.x;
    if (tid == 0) {
        int c = 0; d_cum[0] = 0;
        for (int z = 0; z < Zs; z++) { c += counts[z]; d_cum[z + 1] = c; }
    }
    for (int it = tid; it < Zs * Fc * 12; it += blockDim.x) {
        int z = it / (Fc * 12);
        int rem = it % (Fc * 12);
        int u = rem / 12, b = rem % 12;
        float s = 0.f;
        if (b < 9) {
            #pragma unroll
            for (int p = 0; p < 9; p++)
                s += Wsc[(z * 9 + p) * Fc + u] * Proj[p * 9 + b];
        }
        d_wsc[it] = s;
    }
}

// ---- kA: linear_up + species skip, 25-node tiles x 400 threads ----
constexpr int SMA_FLOATS = 4096 * 4 + 1600 + 4800 + 16;
constexpr int SMA_BYTES  = SMA_FLOATS * 4;
__global__ void __launch_bounds__(400) kA(
    const float* __restrict__ node_s, const float* __restrict__ node_v,
    const float* __restrict__ Wup0, const float* __restrict__ Wup1,
    const float* __restrict__ Ws0, const float* __restrict__ Ws1) {
    extern __shared__ __align__(16) float sm[];
    float* sWup0 = sm;
    float* sWup1 = sm + 4096;
    float* sS0   = sm + 8192;
    float* sS1   = sm + 12288;
    float* sS    = sm + 16384;
    float* sV    = sm + 17984;
    int*   sCum  = (int*)(sm + 22784);

    int tid = threadIdx.x;
    int n0 = blockIdx.x * 25;

    if (tid < Zs + 1) sCum[tid] = d_cum[tid];
    for (int i = tid; i < 25 * 64; i += 400)
        d_acc[n0 * 64 + i] = make_float4(0.f, 0.f, 0.f, 0.f);
    __syncthreads();
    int zA = 0;
    #pragma unroll
    for (int q = 1; q < Zs; q++) zA += (n0 >= sCum[q]);
    int boundary = sCum[zA + 1];

    for (int i = tid; i < 4096; i += 400) {
        sWup0[i] = Wup0[i]; sWup1[i] = Wup1[i];
        sS0[i] = Ws0[zA * 4096 + i]; sS1[i] = Ws1[zA * 4096 + i];
    }
    for (int i = tid; i < 1600; i += 400) sS[i] = node_s[n0 * 64 + i];
    for (int i = tid; i < 4800; i += 400) sV[i] = node_v[n0 * 192 + i];
    __syncthreads();

    int nl = tid >> 4;
    int n  = n0 + nl;
    int g0 = (tid & 15) * 4;
    const float* sSp = sS + nl * 64;
    const float* sVp = sV + nl * 192;

    ull us[2] = {0,0}, ks[2] = {0,0};
    ull uv[3][2] = {{0,0},{0,0},{0,0}};
    ull kv[3][2] = {{0,0},{0,0},{0,0}};
    #pragma unroll 8
    for (int f = 0; f < 64; f++) {
        ulonglong2 w0 = *(const ulonglong2*)(sWup0 + f * 64 + g0);
        ulonglong2 w1 = *(const ulonglong2*)(sWup1 + f * 64 + g0);
        ulonglong2 q0 = *(const ulonglong2*)(sS0 + f * 64 + g0);
        ulonglong2 q1 = *(const ulonglong2*)(sS1 + f * 64 + g0);
        float s = sSp[f];
        float v0 = sVp[f*3], v1 = sVp[f*3+1], v2 = sVp[f*3+2];
        ull ps = pk2(s, s);
        ull p0 = pk2(v0, v0), p1 = pk2(v1, v1), p2 = pk2(v2, v2);
        fma2p(us[0], w0.x, ps); fma2p(us[1], w0.y, ps);
        fma2p(uv[0][0], w1.x, p0); fma2p(uv[0][1], w1.y, p0);
        fma2p(uv[1][0], w1.x, p1); fma2p(uv[1][1], w1.y, p1);
        fma2p(uv[2][0], w1.x, p2); fma2p(uv[2][1], w1.y, p2);
        fma2p(ks[0], q0.x, ps); fma2p(ks[1], q0.y, ps);
        fma2p(kv[0][0], q1.x, p0); fma2p(kv[0][1], q1.y, p0);
        fma2p(kv[1][0], q1.x, p1); fma2p(kv[1][1], q1.y, p1);
        fma2p(kv[2][0], q1.x, p2); fma2p(kv[2][1], q1.y, p2);
    }

    if (n >= boundary) {  // never taken in practice
        int zn = 0;
        #pragma unroll
        for (int q = 1; q < Zs; q++) zn += (n >= sCum[q]);
        const float* g0p = Ws0 + zn * 4096;
        const float* g1p = Ws1 + zn * 4096;
        ks[0] = ks[1] = 0;
        kv[0][0] = kv[0][1] = kv[1][0] = kv[1][1] = kv[2][0] = kv[2][1] = 0;
        for (int f = 0; f < 64; f++) {
            ulonglong2 q0 = *(const ulonglong2*)(g0p + f * 64 + g0);
            ulonglong2 q1 = *(const ulonglong2*)(g1p + f * 64 + g0);
            float s = sSp[f];
            float v0 = sVp[f*3], v1 = sVp[f*3+1], v2 = sVp[f*3+2];
            ull ps = pk2(s, s);
            ull p0 = pk2(v0, v0), p1 = pk2(v1, v1), p2 = pk2(v2, v2);
            fma2p(ks[0], q0.x, ps); fma2p(ks[1], q0.y, ps);
            fma2p(kv[0][0], q1.x, p0); fma2p(kv[0][1], q1.y, p0);
            fma2p(kv[1][0], q1.x, p1); fma2p(kv[1][1], q1.y, p1);
            fma2p(kv[2][0], q1.x, p2); fma2p(kv[2][1], q1.y, p2);
        }
    }

    float a[4], x[4], y[4], z[4];
    float b[4], u[4], v[4], t[4];
    upk2(us[0], a[0], a[1]); upk2(us[1], a[2], a[3]);
    upk2(uv[0][0], x[0], x[1]); upk2(uv[0][1], x[2], x[3]);
    upk2(uv[1][0], y[0], y[1]); upk2(uv[1][1], y[2], y[3]);
    upk2(uv[2][0], z[0], z[1]); upk2(uv[2][1], z[2], z[3]);
    upk2(ks[0], b[0], b[1]); upk2(ks[1], b[2], b[3]);
    upk2(kv[0][0], u[0], u[1]); upk2(kv[0][1], u[2], u[3]);
    upk2(kv[1][0], v[0], v[1]); upk2(kv[1][1], v[2], v[3]);
    upk2(kv[2][0], t[0], t[1]); upk2(kv[2][1], t[2], t[3]);
    #pragma unroll
    for (int j = 0; j < 4; j++) {
        d_uph[n * 64 + g0 + j] = make_uint2(pkhf(a[j]*INV, x[j]*INV), pkhf(y[j]*INV, z[j]*INV));
        d_skip[n * 64 + g0 + j] = make_float4(b[j]*INV, u[j]*INV, v[j]*INV, t[j]*INV);
    }
}

// ================= kB: fp16 mma.sync edge pipeline, 64-edge tiles, 3 CTAs/SM
// In-place activation buffer (no ping-pong); C lives in regs across the
// read->write barrier, so A can be overwritten safely.
constexpr int OF_AH  = 0;        // 64x64 fp16 = 8192
constexpr int OF_AL  = 8192;
constexpr int OF_W2  = 16384;    // 64x64 fp16 = 8192
constexpr int OF_W3  = 24576;
constexpr int OF_W4  = 32768;    // 4 paths x 8192 = 32768
constexpr int OF_U   = 65536;    // 64x3 f32 = 768
constexpr int OF_SND = 66304;    // 64 int
constexpr int OF_RCV = 66560;    // 64 int
constexpr int OF_RE  = 66816;    // 64x8 f32 = 2048
constexpr int OF_R1T = 68864;    // 64x8 f32 = 2048
constexpr int SMB_BYTES = 70912;

// one 64x64 layer, 2 passes: C += Ah*W + Al*W (B fragments shared)
__device__ __forceinline__ void gemm_layer(uint32_t aH, uint32_t aL, uint32_t W,
                                           int mr, int h, int lane, float C[4][4]) {
    #pragma unroll
    for (int ks = 0; ks < 4; ks++) {
        uint32_t ah[4], al[4];
        ldsmA(aH, mr, ks * 16, lane, ah);
        ldsmA(aL, mr, ks * 16, lane, al);
        #pragma unroll
        for (int nt = 0; nt < 4; nt++) {
            uint32_t b[2]; ldsmB(W, ks * 16, h * 32 + nt * 8, lane, b);
            mma16816(C[nt], ah, b);
            mma16816(C[nt], al, b);
        }
    }
}

__global__ void __launch_bounds__(256, 3) kB(
    const float* __restrict__ vectors, const float* __restrict__ radial,
    const int* __restrict__ senders, const int* __restrict__ receivers,
    const float* __restrict__ R1, const float* __restrict__ R2,
    const float* __restrict__ R3, const float* __restrict__ R4) {
    extern __shared__ __align__(1024) char smc[];
    float* smf = (float*)smc;
    uint32_t sb = smem_u32(smc);
    int tid = threadIdx.x;
    int wid = tid >> 5;
    int lane = tid & 31;
    int g = lane >> 2, tg = lane & 3;

    // ---- stage weights: fp16, [k][n] row-major, swizzled ----
    for (int i = tid; i < 4096; i += 256) {
        int k = i >> 6, n = i & 63;
        uint32_t off = SWZ128((uint32_t)(k * 128 + n * 2));
        *(__half*)(smc + OF_W2 + off) = __float2half_rn(R2[k * 64 + n]);
        *(__half*)(smc + OF_W3 + off) = __float2half_rn(R3[k * 64 + n]);
    }
    for (int i = tid; i < 16384; i += 256) {
        int k = i >> 8, c = i & 255;
        int p = c >> 6, f = c & 63;
        uint32_t off = SWZ128((uint32_t)(k * 128 + f * 2));
        *(__half*)(smc + OF_W4 + p * 8192 + off) = __float2half_rn(R4[k * 256 + c]);
    }
    for (int i = tid; i < 512; i += 256) {   // R1 transposed [o][d]
        int o = i >> 3, d = i & 7;
        smf[OF_R1T / 4 + o * 8 + d] = R1[d * 64 + o];
    }
    __syncthreads();

    const float* sU  = smf + OF_U / 4;
    const int* sSnd  = (const int*)(smc + OF_SND);
    const int* sRcv  = (const int*)(smc + OF_RCV);
    const float* sRe = smf + OF_RE / 4;

    int mi = wid & 3, h = wid >> 2;
    int mr = mi * 16;

    for (int t = blockIdx.x; t < Ee / 64; t += gridDim.x) {
        __syncthreads();   // previous tile fully consumed
        int eb0 = t * 64;
        if (tid < 64) {
            int e = eb0 + tid;
            ((int*)(smc + OF_SND))[tid] = senders[e];
            ((int*)(smc + OF_RCV))[tid] = receivers[e];
            const float4* rp = (const float4*)(radial + e * 8);
            *(float4*)(smf + OF_RE / 4 + tid * 8)     = rp[0];
            *(float4*)(smf + OF_RE / 4 + tid * 8 + 4) = rp[1];
            float vx = vectors[e*3], vy = vectors[e*3+1], vz = vectors[e*3+2];
            float rin = rsqrtf(vx*vx + vy*vy + vz*vz);
            smf[OF_U/4 + tid*3] = vx*rin;
            smf[OF_U/4 + tid*3+1] = vy*rin;
            smf[OF_U/4 + tid*3+2] = vz*rin;
        }
        __syncthreads();

        // ---- L1 scalar: A = silu(re @ R1) -> fp16 hi/lo swizzled ----
        {
            int e = tid >> 2, c0 = (tid & 3) * 16;
            float re[8];
            #pragma unroll
            for (int d = 0; d < 8; d++) re[d] = sRe[e * 8 + d];
            float o[16];
            #pragma unroll
            for (int j = 0; j < 16; j++) {
                float acc = 0.f;
                #pragma unroll
                for (int d = 0; d < 8; d++)
                    acc += re[d] * smf[OF_R1T/4 + (c0 + j) * 8 + d];
                o[j] = silu(acc);
            }
            uint32_t hi[8], lo[8];
            #pragma unroll
            for (int j = 0; j < 8; j++) {
                float x0 = o[2*j], x1 = o[2*j+1];
                __half h0 = __float2half_rn(x0), h1 = __float2half_rn(x1);
                hi[j] = pkhf(x0, x1);
                lo[j] = pkhf(x0 - __half2float(h0), x1 - __half2float(h1));
            }
            uint32_t b0 = (uint32_t)(e * 128 + c0 * 2);
            asm volatile("st.shared.v4.b32 [%0], {%1,%2,%3,%4};" ::
                "r"(sb + OF_AH + SWZ128(b0)), "r"(hi[0]), "r"(hi[1]), "r"(hi[2]), "r"(hi[3]) : "memory");
            asm volatile("st.shared.v4.b32 [%0], {%1,%2,%3,%4};" ::
                "r"(sb + OF_AH + SWZ128(b0 + 16)), "r"(hi[4]), "r"(hi[5]), "r"(hi[6]), "r"(hi[7]) : "memory");
            asm volatile("st.shared.v4.b32 [%0], {%1,%2,%3,%4};" ::
                "r"(sb + OF_AL + SWZ128(b0)), "r"(lo[0]), "r"(lo[1]), "r"(lo[2]), "r"(lo[3]) : "memory");
            asm volatile("st.shared.v4.b32 [%0], {%1,%2,%3,%4};" ::
                "r"(sb + OF_AL + SWZ128(b0 + 16)), "r"(lo[4]), "r"(lo[5]), "r"(lo[6]), "r"(lo[7]) : "memory");
        }
        __syncthreads();

        // ---- L2 / L3: in-place (C in regs across the barrier) ----
        #pragma unroll 1
        for (int layer = 0; layer < 2; layer++) {
            uint32_t W = sb + (layer ? OF_W3 : OF_W2);
            float C[4][4];
            #pragma unroll
            for (int nt = 0; nt < 4; nt++)
                #pragma unroll
                for (int j = 0; j < 4; j++) C[nt][j] = 0.f;
            gemm_layer(sb + OF_AH, sb + OF_AL, W, mr, h, lane, C);
            __syncthreads();   // all reads of A complete
            #pragma unroll
            for (int nt = 0; nt < 4; nt++) {
                int colb = (h * 32 + nt * 8 + tg * 2) * 2;
                #pragma unroll
                for (int rh = 0; rh < 2; rh++) {
                    float x0 = silu(C[nt][rh * 2]);
                    float x1 = silu(C[nt][rh * 2 + 1]);
                    __half h0 = __float2half_rn(x0), h1 = __float2half_rn(x1);
                    uint32_t hi = pkhf(x0, x1);
                    uint32_t lo = pkhf(x0 - __half2float(h0), x1 - __half2float(h1));
                    uint32_t off = (uint32_t)((mr + g + rh * 8) * 128 + colb);
                    asm volatile("st.shared.b32 [%0], %1;" :: "r"(sb + OF_AH + SWZ128(off)), "r"(hi) : "memory");
                    asm volatile("st.shared.b32 [%0], %1;" :: "r"(sb + OF_AL + SWZ128(off)), "r"(lo) : "memory");
                }
            }
            __syncthreads();   // writes visible
        }

        // ---- L4: all 4 paths at this warp's 32 channels (reads A) ----
        {
            float C4[16][4];
            #pragma unroll
            for (int i = 0; i < 16; i++)
                #pragma unroll
                for (int j = 0; j < 4; j++) C4[i][j] = 0.f;
            #pragma unroll
            for (int ks = 0; ks < 4; ks++) {
                uint32_t ah[4], al[4];
                ldsmA(sb + OF_AH, mr, ks * 16, lane, ah);
                ldsmA(sb + OF_AL, mr, ks * 16, lane, al);
                #pragma unroll
                for (int p = 0; p < 4; p++) {
                    uint32_t bb = sb + OF_W4 + p * 8192;
                    #pragma unroll
                    for (int nt = 0; nt < 4; nt++) {
                        uint32_t b[2]; ldsmB(bb, ks * 16, h * 32 + nt * 8, lane, b);
                        mma16816(C4[p * 4 + nt], ah, b);
                        mma16816(C4[p * 4 + nt], al, b);
                    }
                }
            }

            // ---- TP + scatter: one packed gather covers both channels ----
            #pragma unroll
            for (int rh = 0; rh < 2; rh++) {
                int el = mr + g + rh * 8;
                int s = sSnd[el], r = sRcv[el];
                float ux = sU[el*3], uy = sU[el*3+1], uz = sU[el*3+2];
                #pragma unroll
                for (int nt = 0; nt < 4; nt++) {
                    int fb = h * 32 + nt * 8 + tg * 2;
                    uint4 up2 = __ldg((const uint4*)(d_uph + (size_t)s * 64 + fb));
                    #pragma unroll
                    for (int j = 0; j < 2; j++) {
                        int f = fb + j;
                        int ci = rh * 2 + j;
                        float w0 = C4[0 * 4 + nt][ci];
                        float w1 = C4[1 * 4 + nt][ci];
                        float w2 = C4[2 * 4 + nt][ci];
                        float w3 = C4[3 * 4 + nt][ci];
                        float2 ab = uphf(j ? up2.z : up2.x);   // (s, v0)
                        float2 cd = uphf(j ? up2.w : up2.y);   // (v1, v2)
                        float dot = ab.y*ux + cd.x*uy + cd.y*uz;
                        float ms = w0 * ab.x + w1 * dot;
                        float c  = w3 * ab.x;
                        red4((float*)(d_acc + (r * 64 + f)),
                             ms, w2*ab.y + c*ux, w2*cd.x + c*uy, w2*cd.y + c*uz);
                    }
                }
            }
        }
    }
}

// ---- kC: linear_down + symmetric contraction + linear_sc + skip + readout ----
constexpr int SMC_FLOATS = 4096 + 4096 + 8192 + 64 + 16;
constexpr int SMC_BYTES  = SMC_FLOATS * 4;
__global__ void __launch_bounds__(512, 3) kC(
    const float* __restrict__ Wd0, const float* __restrict__ Wd1,
    const float* __restrict__ Wl0, const float* __restrict__ Wl1,
    const float* __restrict__ Wr, float* __restrict__ out) {
    extern __shared__ __align__(16) float sm[];
    float* sW0 = sm;
    float* sW1 = sm + 4096;
    float4* sIn  = (float4*)(sm + 8192);   // 2048 float4; reused as sMid
    float* sWr = sm + 16384;
    int* sCum = (int*)(sm + 16448);

    int tid = threadIdx.x;
    int n0 = blockIdx.x * 32;
    for (int i = tid; i < 4096; i += 512) { sW0[i] = Wd0[i]; sW1[i] = Wd1[i]; }
    if (tid < 64) sWr[tid] = Wr[tid];
    if (tid < Zs + 1) sCum[tid] = d_cum[tid];
    for (int i = tid; i < 2048; i += 512) {
        int n = n0 + (i >> 6);
        float4 t = (n < Nn) ? d_acc[n * 64 + (i & 63)] : make_float4(0,0,0,0);
        sIn[i] = make_float4(t.x*EPSC, t.y*EPSC, t.z*EPSC, t.w*EPSC);
    }
    __syncthreads();

    int nl = tid >> 4;
    int n  = n0 + nl;
    int g0 = (tid & 15) * 4;
    bool valid = (n < Nn);
    float* ohv = out + Nn + Nn * 64;

    ull hs_[2] = {0,0};
    ull hv_[3][2] = {{0,0},{0,0},{0,0}};
    #pragma unroll 8
    for (int fi = 0; fi < 64; fi++) {
        ulonglong2 w0 = *(const ulonglong2*)(sW0 + fi * 64 + g0);
        ulonglong2 w1 = *(const ulonglong2*)(sW1 + fi * 64 + g0);
        float4 a = sIn[nl * 64 + fi];
        ull ps = pk2(a.x, a.x);
        ull p0 = pk2(a.y, a.y), p1 = pk2(a.z, a.z), p2 = pk2(a.w, a.w);
        fma2p(hs_[0], w0.x, ps); fma2p(hs_[1], w0.y, ps);
        fma2p(hv_[0][0], w1.x, p0); fma2p(hv_[0][1], w1.y, p0);
        fma2p(hv_[1][0], w1.x, p1); fma2p(hv_[1][1], w1.y, p1);
        fma2p(hv_[2][0], w1.x, p2); fma2p(hv_[2][1], w1.y, p2);
    }
    float hs[4], hx[4], hy[4], hz[4];
    upk2(hs_[0], hs[0], hs[1]); upk2(hs_[1], hs[2], hs[3]);
    upk2(hv_[0][0], hx[0], hx[1]); upk2(hv_[0][1], hx[2], hx[3]);
    upk2(hv_[1][0], hy[0], hy[1]); upk2(hv_[1][1], hy[2], hy[3]);
    upk2(hv_[2][0], hz[0], hz[1]); upk2(hv_[2][1], hz[2], hz[3]);

    __syncwarp();   // all stage-1 reads of this warp's rows complete
    if (valid) {
        int z = 0;
        #pragma unroll
        for (int q = 1; q < Zs; q++) z += (n >= sCum[q]);
        #pragma unroll
        for (int j = 0; j < 4; j++) {
            const float* wp = d_wsc + (size_t)(z * 64 + g0 + j) * 12;
            float4 wa = *(const float4*)wp;
            float4 wb = *(const float4*)(wp + 4);
            float  wc = wp[8];
            float h = hs[j] * INV;
            float x = hx[j] * INV, y = hy[j] * INV, zc = hz[j] * INV;
            float vv = x*x + y*y + zc*zc;
            float h2 = h * h;
            float cs = wa.x*h + wa.y*h2 + wa.z*vv + wa.w*(h2*h) + wb.x*(h*vv);
            float cf = wb.y + wb.z*h + wb.w*h2 + wc*vv;
            sIn[nl * 64 + g0 + j] = make_float4(cs, x*cf, y*cf, zc*cf);
        }
    }
    __syncthreads();
    for (int i = tid; i < 4096; i += 512) { sW0[i] = Wl0[i]; sW1[i] = Wl1[i]; }
    __syncthreads();

    float partial = 0.f;
    if (valid) {
        ull cs_[2] = {0,0};
        ull cv_[3][2] = {{0,0},{0,0},{0,0}};
        #pragma unroll 8
        for (int fi = 0; fi < 64; fi++) {
            ulonglong2 w0 = *(const ulonglong2*)(sW0 + fi * 64 + g0);
            ulonglong2 w1 = *(const ulonglong2*)(sW1 + fi * 64 + g0);
            float4 a = sIn[nl * 64 + fi];
            ull ps = pk2(a.x, a.x);
            ull p0 = pk2(a.y, a.y), p1 = pk2(a.z, a.z), p2 = pk2(a.w, a.w);
            fma2p(cs_[0], w0.x, ps); fma2p(cs_[1], w0.y, ps);
            fma2p(cv_[0][0], w1.x, p0); fma2p(cv_[0][1], w1.y, p0);
            fma2p(cv_[1][0], w1.x, p1); fma2p(cv_[1][1], w1.y, p1);
            fma2p(cv_[2][0], w1.x, p2); fma2p(cv_[2][1], w1.y, p2);
        }
        float cs[4], cx[4], cy[4], cz[4];
        upk2(cs_[0], cs[0], cs[1]); upk2(cs_[1], cs[2], cs[3]);
        upk2(cv_[0][0], cx[0], cx[1]); upk2(cv_[0][1], cx[2], cx[3]);
        upk2(cv_[1][0], cy[0], cy[1]); upk2(cv_[1][1], cy[2], cy[3]);
        upk2(cv_[2][0], cz[0], cz[1]); upk2(cv_[2][1], cz[2], cz[3]);
        #pragma unroll
        for (int j = 0; j < 4; j++) {
            int g = g0 + j;
            float4 sk = d_skip[n * 64 + g];
            float hso = cs[j]*INV + sk.x;
            float v0 = cx[j]*INV + sk.y;
            float v1 = cy[j]*INV + sk.z;
            float v2 = cz[j]*INV + sk.w;
            out[Nn + n * 64 + g] = hso;
            ohv[(n * 64 + g) * 3 + 0] = v0;
            ohv[(n * 64 + g) * 3 + 1] = v1;
            ohv[(n * 64 + g) * 3 + 2] = v2;
            partial += hso * sWr[g];
        }
    }
    partial += __shfl_down_sync(0xffffffffu, partial, 8, 16);
    partial += __shfl_down_sync(0xffffffffu, partial, 4, 16);
    partial += __shfl_down_sync(0xffffffffu, partial, 2, 16);
    partial += __shfl_down_sync(0xffffffffu, partial, 1, 16);
    if ((tid & 15) == 0 && valid) out[n] = partial * INV;
}

extern "C" void kernel_launch(void* const* d_in, const int* in_sizes, int n_in,
                              void* d_out, int out_size) {
    (void)in_sizes; (void)n_in; (void)out_size;
    const float* vectors   = (const float*)d_in[0];
    const float* node_s    = (const float*)d_in[1];
    const float* node_v    = (const float*)d_in[2];
    const float* radial    = (const float*)d_in[3];
    const int*   senders   = (const int*)d_in[4];
    const int*   receivers = (const int*)d_in[5];
    const int*   counts    = (const int*)d_in[6];
    const float* Wup0 = (const float*)d_in[7];
    const float* Wup1 = (const float*)d_in[8];
    const float* R1   = (const float*)d_in[9];
    const float* R2   = (const float*)d_in[10];
    const float* R3   = (const float*)d_in[11];
    const float* R4   = (const float*)d_in[12];
    const float* Wd0  = (const float*)d_in[13];
    const float* Wd1  = (const float*)d_in[14];
    const float* Ws0  = (const float*)d_in[15];
    const float* Ws1  = (const float*)d_in[16];
    const float* Wsc  = (const float*)d_in[17];
    const float* Proj = (const float*)d_in[18];
    const float* Wl0  = (const float*)d_in[19];
    const float* Wl1  = (const float*)d_in[20];
    const float* Wr   = (const float*)d_in[21];
    float* out = (float*)d_out;

    cudaFuncSetAttribute(kA, cudaFuncAttributeMaxDynamicSharedMemorySize, SMA_BYTES);
    cudaFuncSetAttribute(kB, cudaFuncAttributeMaxDynamicSharedMemorySize, SMB_BYTES);
    cudaFuncSetAttribute(kC, cudaFuncAttributeMaxDynamicSharedMemorySize, SMC_BYTES);

    k0<<<1, 256>>>(counts, Wsc, Proj);
    kA<<<Nn / 25, 400, SMA_BYTES>>>(node_s, node_v, Wup0, Wup1, Ws0, Ws1);
    kB<<<456, 256, SMB_BYTES>>>(vectors, radial, senders, receivers, R1, R2, R3, R4);
    kC<<<(Nn + 31) / 32, 512, SMC_BYTES>>>(Wd0, Wd1, Wl0, Wl1, Wr, out);
}

// round 16
// speedup vs baseline: 1.0969x; 1.0969x over previous
#include <cuda_runtime.h>
#include <cuda_fp16.h>
#include <cstdint>

#define Nn 20000
#define Fc 64
#define Zs 10
#define Ee 320000

// ---- scratch (device globals; no allocation) ----
__device__ uint2  d_uph[Nn * Fc];     // fp16-packed (s,v0|v1,v2), inv folded
__device__ float4 d_skip[Nn * Fc];    // packed skip, inv folded
__device__ float4 d_acc[Nn * Fc];     // message accumulator (memset by host)
__device__ float  d_wsc[Zs * 9 * Fc]; // Wsc projected: [(z*9+b)*64+u]
__device__ int    d_cum[Zs + 1];

constexpr float INV  = 0.125f;  // 1/sqrt(64)
constexpr float EPSC = 0.25f;

typedef unsigned long long ull;

__device__ __forceinline__ float silu(float x) {
    return __fdividef(x, 1.0f + __expf(-x));
}
__device__ __forceinline__ ull pk2(float a, float b) {
    ull r; asm("mov.b64 %0, {%1, %2};" : "=l"(r) : "f"(a), "f"(b)); return r;
}
__device__ __forceinline__ void upk2(ull v, float& a, float& b) {
    asm("mov.b64 {%0, %1}, %2;" : "=f"(a), "=f"(b) : "l"(v));
}
__device__ __forceinline__ void fma2p(ull& d, ull a, ull b) {
    asm("fma.rn.f32x2 %0, %1, %2, %0;" : "+l"(d) : "l"(a), "l"(b));
}
__device__ __forceinline__ void red4(float* p, float a, float b, float c, float d) {
    ull gp = (ull)__cvta_generic_to_global(p);
    asm volatile("red.global.add.v4.f32 [%0], {%1, %2, %3, %4};"
                 :: "l"(gp), "f"(a), "f"(b), "f"(c), "f"(d) : "memory");
}
__device__ __forceinline__ uint32_t smem_u32(const void* p) {
    uint32_t a;
    asm("{ .reg .u64 t; cvta.to.shared.u64 t, %1; cvt.u32.u64 %0, t; }"
        : "=r"(a) : "l"(p));
    return a;
}
#define SWZ128(b) ((b) ^ (((b) >> 3) & 0x70))

__device__ __forceinline__ uint32_t pkhf(float a, float b) {
    __half2 t = __floats2half2_rn(a, b);
    return *(uint32_t*)&t;
}
__device__ __forceinline__ float2 uphf(uint32_t v) {
    return __half22float2(*(__half2*)&v);
}

// ---- warp-level mma.sync helpers (fp16 in, fp32 accum) ----
__device__ __forceinline__ void ldsmA(uint32_t base, int mr, int k0, int lane, uint32_t a[4]) {
    int row = mr + (lane & 7) + ((lane >> 3) & 1) * 8;
    int col = k0 + (lane >> 4) * 8;
    uint32_t off = (uint32_t)(row * 128 + col * 2);
    uint32_t addr = base + SWZ128(off);
    asm volatile("ldmatrix.sync.aligned.m8n8.x4.shared.b16 {%0,%1,%2,%3}, [%4];"
        : "=r"(a[0]), "=r"(a[1]), "=r"(a[2]), "=r"(a[3]) : "r"(addr));
}
__device__ __forceinline__ void ldsmB(uint32_t base, int k0, int n0, int lane, uint32_t b[2]) {
    int k = k0 + (lane & 15);
    uint32_t off = (uint32_t)(k * 128 + n0 * 2);
    uint32_t addr = base + SWZ128(off);
    asm volatile("ldmatrix.sync.aligned.m8n8.x2.trans.shared.b16 {%0,%1}, [%2];"
        : "=r"(b[0]), "=r"(b[1]) : "r"(addr));
}
__device__ __forceinline__ void mma16816(float c[4], const uint32_t a[4], const uint32_t b[2]) {
    asm volatile("mma.sync.aligned.m16n8k16.row.col.f32.f16.f16.f32 "
        "{%0,%1,%2,%3}, {%4,%5,%6,%7}, {%8,%9}, {%0,%1,%2,%3};"
        : "+f"(c[0]), "+f"(c[1]), "+f"(c[2]), "+f"(c[3])
        : "r"(a[0]), "r"(a[1]), "r"(a[2]), "r"(a[3]), "r"(b[0]), "r"(b[1]));
}

// ---- k0: species prefix + Wsc @ Proj ----
__global__ void k0(const int* __restrict__ counts,
                   const float* __restrict__ Wsc,
                   const float* __restrict__ Proj) {
    int tid = threadIdx.x;
    if (tid == 0) {
        int c = 0; d_cum[0] = 0;
        for (int z = 0; z < Zs; z++) { c += counts[z]; d_cum[z + 1] = c; }
    }
    for (int it = tid; it < Zs * 9 * Fc; it += blockDim.x) {
        int z = it / (9 * Fc);
        int rem = it % (9 * Fc);
        int b = rem / Fc, u = rem % Fc;
        float s = 0.f;
        #pragma unroll
        for (int p = 0; p < 9; p++)
            s += Wsc[(z * 9 + p) * Fc + u] * Proj[p * 9 + b];
        d_wsc[it] = s;
    }
}

// ---- kA: linear_up + species skip, 25-node tiles x 400 threads ----
constexpr int SMA_FLOATS = 4096 * 4 + 1600 + 4800 + 16;
constexpr int SMA_BYTES  = SMA_FLOATS * 4;
__global__ void __launch_bounds__(400) kA(
    const float* __restrict__ node_s, const float* __restrict__ node_v,
    const float* __restrict__ Wup0, const float* __restrict__ Wup1,
    const float* __restrict__ Ws0, const float* __restrict__ Ws1) {
    extern __shared__ __align__(16) float sm[];
    float* sWup0 = sm;
    float* sWup1 = sm + 4096;
    float* sS0   = sm + 8192;
    float* sS1   = sm + 12288;
    float* sS    = sm + 16384;
    float* sV    = sm + 17984;
    int*   sCum  = (int*)(sm + 22784);

    int tid = threadIdx.x;
    int n0 = blockIdx.x * 25;

    if (tid < Zs + 1) sCum[tid] = d_cum[tid];
    __syncthreads();
    int zA = 0;
    #pragma unroll
    for (int q = 1; q < Zs; q++) zA += (n0 >= sCum[q]);
    int boundary = sCum[zA + 1];

    for (int i = tid; i < 4096; i += 400) {
        sWup0[i] = Wup0[i]; sWup1[i] = Wup1[i];
        sS0[i] = Ws0[zA * 4096 + i]; sS1[i] = Ws1[zA * 4096 + i];
    }
    for (int i = tid; i < 1600; i += 400) sS[i] = node_s[n0 * 64 + i];
    for (int i = tid; i < 4800; i += 400) sV[i] = node_v[n0 * 192 + i];
    __syncthreads();

    int nl = tid >> 4;
    int n  = n0 + nl;
    int g0 = (tid & 15) * 4;
    const float* sSp = sS + nl * 64;
    const float* sVp = sV + nl * 192;

    ull us[2] = {0,0}, ks[2] = {0,0};
    ull uv[3][2] = {{0,0},{0,0},{0,0}};
    ull kv[3][2] = {{0,0},{0,0},{0,0}};
    #pragma unroll 8
    for (int f = 0; f < 64; f++) {
        ulonglong2 w0 = *(const ulonglong2*)(sWup0 + f * 64 + g0);
        ulonglong2 w1 = *(const ulonglong2*)(sWup1 + f * 64 + g0);
        ulonglong2 q0 = *(const ulonglong2*)(sS0 + f * 64 + g0);
        ulonglong2 q1 = *(const ulonglong2*)(sS1 + f * 64 + g0);
        float s = sSp[f];
        float v0 = sVp[f*3], v1 = sVp[f*3+1], v2 = sVp[f*3+2];
        ull ps = pk2(s, s);
        ull p0 = pk2(v0, v0), p1 = pk2(v1, v1), p2 = pk2(v2, v2);
        fma2p(us[0], w0.x, ps); fma2p(us[1], w0.y, ps);
        fma2p(uv[0][0], w1.x, p0); fma2p(uv[0][1], w1.y, p0);
        fma2p(uv[1][0], w1.x, p1); fma2p(uv[1][1], w1.y, p1);
        fma2p(uv[2][0], w1.x, p2); fma2p(uv[2][1], w1.y, p2);
        fma2p(ks[0], q0.x, ps); fma2p(ks[1], q0.y, ps);
        fma2p(kv[0][0], q1.x, p0); fma2p(kv[0][1], q1.y, p0);
        fma2p(kv[1][0], q1.x, p1); fma2p(kv[1][1], q1.y, p1);
        fma2p(kv[2][0], q1.x, p2); fma2p(kv[2][1], q1.y, p2);
    }

    if (n >= boundary) {  // never taken in practice
        int zn = 0;
        #pragma unroll
        for (int q = 1; q < Zs; q++) zn += (n >= sCum[q]);
        const float* g0p = Ws0 + zn * 4096;
        const float* g1p = Ws1 + zn * 4096;
        ks[0] = ks[1] = 0;
        kv[0][0] = kv[0][1] = kv[1][0] = kv[1][1] = kv[2][0] = kv[2][1] = 0;
        for (int f = 0; f < 64; f++) {
            ulonglong2 q0 = *(const ulonglong2*)(g0p + f * 64 + g0);
            ulonglong2 q1 = *(const ulonglong2*)(g1p + f * 64 + g0);
            float s = sSp[f];
            float v0 = sVp[f*3], v1 = sVp[f*3+1], v2 = sVp[f*3+2];
            ull ps = pk2(s, s);
            ull p0 = pk2(v0, v0), p1 = pk2(v1, v1), p2 = pk2(v2, v2);
            fma2p(ks[0], q0.x, ps); fma2p(ks[1], q0.y, ps);
            fma2p(kv[0][0], q1.x, p0); fma2p(kv[0][1], q1.y, p0);
            fma2p(kv[1][0], q1.x, p1); fma2p(kv[1][1], q1.y, p1);
            fma2p(kv[2][0], q1.x, p2); fma2p(kv[2][1], q1.y, p2);
        }
    }

    float a[4], x[4], y[4], z[4];
    float b[4], u[4], v[4], t[4];
    upk2(us[0], a[0], a[1]); upk2(us[1], a[2], a[3]);
    upk2(uv[0][0], x[0], x[1]); upk2(uv[0][1], x[2], x[3]);
    upk2(uv[1][0], y[0], y[1]); upk2(uv[1][1], y[2], y[3]);
    upk2(uv[2][0], z[0], z[1]); upk2(uv[2][1], z[2], z[3]);
    upk2(ks[0], b[0], b[1]); upk2(ks[1], b[2], b[3]);
    upk2(kv[0][0], u[0], u[1]); upk2(kv[0][1], u[2], u[3]);
    upk2(kv[1][0], v[0], v[1]); upk2(kv[1][1], v[2], v[3]);
    upk2(kv[2][0], t[0], t[1]); upk2(kv[2][1], t[2], t[3]);
    #pragma unroll
    for (int j = 0; j < 4; j++) {
        d_uph[n * 64 + g0 + j] = make_uint2(pkhf(a[j]*INV, x[j]*INV), pkhf(y[j]*INV, z[j]*INV));
        d_skip[n * 64 + g0 + j] = make_float4(b[j]*INV, u[j]*INV, v[j]*INV, t[j]*INV);
    }
}

// ================= kB: fp16 mma.sync edge pipeline, 64-edge tiles, 2 CTAs/SM
constexpr int OF_AH  = 0;        // 64x64 fp16 = 8192
constexpr int OF_AL  = 8192;
constexpr int OF_DH  = 16384;
constexpr int OF_DL  = 24576;
constexpr int OF_W2  = 32768;    // 64x64 fp16 = 8192
constexpr int OF_W3  = 40960;
constexpr int OF_W4  = 49152;    // 4 paths x 8192 = 32768
constexpr int OF_U   = 81920;    // 64x3 f32 = 768
constexpr int OF_SND = 82688;    // 64 int
constexpr int OF_RCV = 82944;    // 64 int
constexpr int OF_RE  = 83200;    // 64x8 f32 = 2048
constexpr int OF_R1T = 85248;    // 64x8 f32 = 2048
constexpr int SMB_BYTES = 87296;

// one 64x64 layer, 2 passes: C += Ah*W + Al*W (B fragments shared)
__device__ __forceinline__ void gemm_layer(uint32_t aH, uint32_t aL, uint32_t W,
                                           int mr, int h, int lane, float C[4][4]) {
    #pragma unroll
    for (int ks = 0; ks < 4; ks++) {
        uint32_t ah[4], al[4];
        ldsmA(aH, mr, ks * 16, lane, ah);
        ldsmA(aL, mr, ks * 16, lane, al);
        #pragma unroll
        for (int nt = 0; nt < 4; nt++) {
            uint32_t b[2]; ldsmB(W, ks * 16, h * 32 + nt * 8, lane, b);
            mma16816(C[nt], ah, b);
            mma16816(C[nt], al, b);
        }
    }
}

__global__ void __launch_bounds__(256, 2) kB(
    const float* __restrict__ vectors, const float* __restrict__ radial,
    const int* __restrict__ senders, const int* __restrict__ receivers,
    const float* __restrict__ R1, const float* __restrict__ R2,
    const float* __restrict__ R3, const float* __restrict__ R4) {
    extern __shared__ __align__(1024) char smc[];
    float* smf = (float*)smc;
    uint32_t sb = smem_u32(smc);
    int tid = threadIdx.x;
    int wid = tid >> 5;
    int lane = tid & 31;
    int g = lane >> 2, tg = lane & 3;

    // ---- stage weights: fp16, [k][n] row-major, swizzled ----
    for (int i = tid; i < 4096; i += 256) {
        int k = i >> 6, n = i & 63;
        uint32_t off = SWZ128((uint32_t)(k * 128 + n * 2));
        *(__half*)(smc + OF_W2 + off) = __float2half_rn(R2[k * 64 + n]);
        *(__half*)(smc + OF_W3 + off) = __float2half_rn(R3[k * 64 + n]);
    }
    for (int i = tid; i < 16384; i += 256) {
        int k = i >> 8, c = i & 255;
        int p = c >> 6, f = c & 63;
        uint32_t off = SWZ128((uint32_t)(k * 128 + f * 2));
        *(__half*)(smc + OF_W4 + p * 8192 + off) = __float2half_rn(R4[k * 256 + c]);
    }
    for (int i = tid; i < 512; i += 256) {   // R1 transposed [o][d]
        int o = i >> 3, d = i & 7;
        smf[OF_R1T / 4 + o * 8 + d] = R1[d * 64 + o];
    }
    __syncthreads();

    const float* sU  = smf + OF_U / 4;
    const int* sSnd  = (const int*)(smc + OF_SND);
    const int* sRcv  = (const int*)(smc + OF_RCV);
    const float* sRe = smf + OF_RE / 4;

    int mi = wid & 3, h = wid >> 2;
    int mr = mi * 16;

    for (int t = blockIdx.x; t < Ee / 64; t += gridDim.x) {
        __syncthreads();   // previous tile fully consumed
        int eb0 = t * 64;
        if (tid < 64) {
            int e = eb0 + tid;
            ((int*)(smc + OF_SND))[tid] = senders[e];
            ((int*)(smc + OF_RCV))[tid] = receivers[e];
            const float4* rp = (const float4*)(radial + e * 8);
            *(float4*)(smf + OF_RE / 4 + tid * 8)     = rp[0];
            *(float4*)(smf + OF_RE / 4 + tid * 8 + 4) = rp[1];
            float vx = vectors[e*3], vy = vectors[e*3+1], vz = vectors[e*3+2];
            float rin = rsqrtf(vx*vx + vy*vy + vz*vz);
            smf[OF_U/4 + tid*3] = vx*rin;
            smf[OF_U/4 + tid*3+1] = vy*rin;
            smf[OF_U/4 + tid*3+2] = vz*rin;
        }
        __syncthreads();

        // ---- L1 scalar: A = silu(re @ R1) -> fp16 hi/lo swizzled ----
        {
            int e = tid >> 2, c0 = (tid & 3) * 16;
            float re[8];
            #pragma unroll
            for (int d = 0; d < 8; d++) re[d] = sRe[e * 8 + d];
            float o[16];
            #pragma unroll
            for (int j = 0; j < 16; j++) {
                float acc = 0.f;
                #pragma unroll
                for (int d = 0; d < 8; d++)
                    acc += re[d] * smf[OF_R1T/4 + (c0 + j) * 8 + d];
                o[j] = silu(acc);
            }
            uint32_t hi[8], lo[8];
            #pragma unroll
            for (int j = 0; j < 8; j++) {
                float x0 = o[2*j], x1 = o[2*j+1];
                __half h0 = __float2half_rn(x0), h1 = __float2half_rn(x1);
                hi[j] = pkhf(x0, x1);
                lo[j] = pkhf(x0 - __half2float(h0), x1 - __half2float(h1));
            }
            uint32_t b0 = (uint32_t)(e * 128 + c0 * 2);
            asm volatile("st.shared.v4.b32 [%0], {%1,%2,%3,%4};" ::
                "r"(sb + OF_AH + SWZ128(b0)), "r"(hi[0]), "r"(hi[1]), "r"(hi[2]), "r"(hi[3]) : "memory");
            asm volatile("st.shared.v4.b32 [%0], {%1,%2,%3,%4};" ::
                "r"(sb + OF_AH + SWZ128(b0 + 16)), "r"(hi[4]), "r"(hi[5]), "r"(hi[6]), "r"(hi[7]) : "memory");
            asm volatile("st.shared.v4.b32 [%0], {%1,%2,%3,%4};" ::
                "r"(sb + OF_AL + SWZ128(b0)), "r"(lo[0]), "r"(lo[1]), "r"(lo[2]), "r"(lo[3]) : "memory");
            asm volatile("st.shared.v4.b32 [%0], {%1,%2,%3,%4};" ::
                "r"(sb + OF_AL + SWZ128(b0 + 16)), "r"(lo[4]), "r"(lo[5]), "r"(lo[6]), "r"(lo[7]) : "memory");
        }
        __syncthreads();

        // ---- L2: reads A, writes D ---- / ---- L3: reads D, writes A ----
        #pragma unroll 1
        for (int layer = 0; layer < 2; layer++) {
            uint32_t inH  = sb + (layer ? OF_DH : OF_AH);
            uint32_t inL  = sb + (layer ? OF_DL : OF_AL);
            uint32_t outH = sb + (layer ? OF_AH : OF_DH);
            uint32_t outL = sb + (layer ? OF_AL : OF_DL);
            uint32_t W = sb + (layer ? OF_W3 : OF_W2);
            float C[4][4];
            #pragma unroll
            for (int nt = 0; nt < 4; nt++)
                #pragma unroll
                for (int j = 0; j < 4; j++) C[nt][j] = 0.f;
            gemm_layer(inH, inL, W, mr, h, lane, C);
            #pragma unroll
            for (int nt = 0; nt < 4; nt++) {
                int colb = (h * 32 + nt * 8 + tg * 2) * 2;
                #pragma unroll
                for (int rh = 0; rh < 2; rh++) {
                    float x0 = silu(C[nt][rh * 2]);
                    float x1 = silu(C[nt][rh * 2 + 1]);
                    __half h0 = __float2half_rn(x0), h1 = __float2half_rn(x1);
                    uint32_t hi = pkhf(x0, x1);
                    uint32_t lo = pkhf(x0 - __half2float(h0), x1 - __half2float(h1));
                    uint32_t off = (uint32_t)((mr + g + rh * 8) * 128 + colb);
                    asm volatile("st.shared.b32 [%0], %1;" :: "r"(outH + SWZ128(off)), "r"(hi) : "memory");
                    asm volatile("st.shared.b32 [%0], %1;" :: "r"(outL + SWZ128(off)), "r"(lo) : "memory");
                }
            }
            __syncthreads();
        }

        // ---- L4: prefetch gathers, then MMA, then TP + scatter ----
        {
            int el0 = mr + g, el1 = el0 + 8;
            int s0 = sSnd[el0], s1 = sSnd[el1];
            int r0 = sRcv[el0], r1 = sRcv[el1];
            float u0x = sU[el0*3], u0y = sU[el0*3+1], u0z = sU[el0*3+2];
            float u1x = sU[el1*3], u1y = sU[el1*3+1], u1z = sU[el1*3+2];
            uint4 pre0[4], pre1[4];
            #pragma unroll
            for (int nt = 0; nt < 4; nt++) {
                int fb = h * 32 + nt * 8 + tg * 2;
                pre0[nt] = __ldg((const uint4*)(d_uph + (size_t)s0 * 64 + fb));
                pre1[nt] = __ldg((const uint4*)(d_uph + (size_t)s1 * 64 + fb));
            }

            float C4[16][4];
            #pragma unroll
            for (int i = 0; i < 16; i++)
                #pragma unroll
                for (int j = 0; j < 4; j++) C4[i][j] = 0.f;
            #pragma unroll
            for (int ks = 0; ks < 4; ks++) {
                uint32_t ah[4], al[4];
                ldsmA(sb + OF_AH, mr, ks * 16, lane, ah);
                ldsmA(sb + OF_AL, mr, ks * 16, lane, al);
                #pragma unroll
                for (int p = 0; p < 4; p++) {
                    uint32_t bb = sb + OF_W4 + p * 8192;
                    #pragma unroll
                    for (int nt = 0; nt < 4; nt++) {
                        uint32_t b[2]; ldsmB(bb, ks * 16, h * 32 + nt * 8, lane, b);
                        mma16816(C4[p * 4 + nt], ah, b);
                        mma16816(C4[p * 4 + nt], al, b);
                    }
                }
            }

            #pragma unroll
            for (int rh = 0; rh < 2; rh++) {
                int r = rh ? r1 : r0;
                float ux = rh ? u1x : u0x;
                float uy = rh ? u1y : u0y;
                float uz = rh ? u1z : u0z;
                #pragma unroll
                for (int nt = 0; nt < 4; nt++) {
                    int fb = h * 32 + nt * 8 + tg * 2;
                    uint4 up2 = rh ? pre1[nt] : pre0[nt];
                    #pragma unroll
                    for (int j = 0; j < 2; j++) {
                        int f = fb + j;
                        int ci = rh * 2 + j;
                        float w0 = C4[0 * 4 + nt][ci];
                        float w1 = C4[1 * 4 + nt][ci];
                        float w2 = C4[2 * 4 + nt][ci];
                        float w3 = C4[3 * 4 + nt][ci];
                        float2 ab = uphf(j ? up2.z : up2.x);   // (s, v0)
                        float2 cd = uphf(j ? up2.w : up2.y);   // (v1, v2)
                        float dot = ab.y*ux + cd.x*uy + cd.y*uz;
                        float ms = w0 * ab.x + w1 * dot;
                        float c  = w3 * ab.x;
                        red4((float*)(d_acc + (r * 64 + f)),
                             ms, w2*ab.y + c*ux, w2*cd.x + c*uy, w2*cd.y + c*uz);
                    }
                }
            }
        }
    }
}

// ---- kC: linear_down + symmetric contraction + linear_sc + skip + readout ----
constexpr int SMC_FLOATS = 4096 + 4096 + 8192 + 64 + 16;
constexpr int SMC_BYTES  = SMC_FLOATS * 4;
__global__ void __launch_bounds__(512, 3) kC(
    const float* __restrict__ Wd0, const float* __restrict__ Wd1,
    const float* __restrict__ Wl0, const float* __restrict__ Wl1,
    const float* __restrict__ Wr, float* __restrict__ out) {
    extern __shared__ __align__(16) float sm[];
    float* sW0 = sm;
    float* sW1 = sm + 4096;
    float4* sIn  = (float4*)(sm + 8192);   // 2048 float4; reused as sMid
    float* sWr = sm + 16384;
    int* sCum = (int*)(sm + 16448);

    int tid = threadIdx.x;
    int n0 = blockIdx.x * 32;
    for (int i = tid; i < 4096; i += 512) { sW0[i] = Wd0[i]; sW1[i] = Wd1[i]; }
    if (tid < 64) sWr[tid] = Wr[tid];
    if (tid < Zs + 1) sCum[tid] = d_cum[tid];
    for (int i = tid; i < 2048; i += 512) {
        int n = n0 + (i >> 6);
        float4 t = (n < Nn) ? d_acc[n * 64 + (i & 63)] : make_float4(0,0,0,0);
        sIn[i] = make_float4(t.x*EPSC, t.y*EPSC, t.z*EPSC, t.w*EPSC);
    }
    __syncthreads();

    int nl = tid >> 4;
    int n  = n0 + nl;
    int g0 = (tid & 15) * 4;
    bool valid = (n < Nn);
    float* ohv = out + Nn + Nn * 64;

    ull hs_[2] = {0,0};
    ull hv_[3][2] = {{0,0},{0,0},{0,0}};
    #pragma unroll 8
    for (int fi = 0; fi < 64; fi++) {
        ulonglong2 w0 = *(const ulonglong2*)(sW0 + fi * 64 + g0);
        ulonglong2 w1 = *(const ulonglong2*)(sW1 + fi * 64 + g0);
        float4 a = sIn[nl * 64 + fi];
        ull ps = pk2(a.x, a.x);
        ull p0 = pk2(a.y, a.y), p1 = pk2(a.z, a.z), p2 = pk2(a.w, a.w);
        fma2p(hs_[0], w0.x, ps); fma2p(hs_[1], w0.y, ps);
        fma2p(hv_[0][0], w1.x, p0); fma2p(hv_[0][1], w1.y, p0);
        fma2p(hv_[1][0], w1.x, p1); fma2p(hv_[1][1], w1.y, p1);
        fma2p(hv_[2][0], w1.x, p2); fma2p(hv_[2][1], w1.y, p2);
    }
    float hs[4], hx[4], hy[4], hz[4];
    upk2(hs_[0], hs[0], hs[1]); upk2(hs_[1], hs[2], hs[3]);
    upk2(hv_[0][0], hx[0], hx[1]); upk2(hv_[0][1], hx[2], hx[3]);
    upk2(hv_[1][0], hy[0], hy[1]); upk2(hv_[1][1], hy[2], hy[3]);
    upk2(hv_[2][0], hz[0], hz[1]); upk2(hv_[2][1], hz[2], hz[3]);

    __syncwarp();   // all stage-1 reads of this warp's rows complete
    if (valid) {
        int z = 0;
        #pragma unroll
        for (int q = 1; q < Zs; q++) z += (n >= sCum[q]);
        const float* wp = d_wsc + z * 576 + g0;
        #pragma unroll
        for (int j = 0; j < 4; j++) {
            float h = hs[j] * INV;
            float x = hx[j] * INV, y = hy[j] * INV, zc = hz[j] * INV;
            float vv = x*x + y*y + zc*zc;
            float h2 = h * h;
            const float* q2 = wp + j;
            float cs = q2[0]*h + q2[64]*h2 + q2[128]*vv + q2[192]*(h2*h) + q2[256]*(h*vv);
            float cf = q2[320] + q2[384]*h + q2[448]*h2 + q2[512]*vv;
            sIn[nl * 64 + g0 + j] = make_float4(cs, x*cf, y*cf, zc*cf);
        }
    }
    __syncthreads();
    for (int i = tid; i < 4096; i += 512) { sW0[i] = Wl0[i]; sW1[i] = Wl1[i]; }
    __syncthreads();

    float partial = 0.f;
    if (valid) {
        ull cs_[2] = {0,0};
        ull cv_[3][2] = {{0,0},{0,0},{0,0}};
        #pragma unroll 8
        for (int fi = 0; fi < 64; fi++) {
            ulonglong2 w0 = *(const ulonglong2*)(sW0 + fi * 64 + g0);
            ulonglong2 w1 = *(const ulonglong2*)(sW1 + fi * 64 + g0);
            float4 a = sIn[nl * 64 + fi];
            ull ps = pk2(a.x, a.x);
            ull p0 = pk2(a.y, a.y), p1 = pk2(a.z, a.z), p2 = pk2(a.w, a.w);
            fma2p(cs_[0], w0.x, ps); fma2p(cs_[1], w0.y, ps);
            fma2p(cv_[0][0], w1.x, p0); fma2p(cv_[0][1], w1.y, p0);
            fma2p(cv_[1][0], w1.x, p1); fma2p(cv_[1][1], w1.y, p1);
            fma2p(cv_[2][0], w1.x, p2); fma2p(cv_[2][1], w1.y, p2);
        }
        float cs[4], cx[4], cy[4], cz[4];
        upk2(cs_[0], cs[0], cs[1]); upk2(cs_[1], cs[2], cs[3]);
        upk2(cv_[0][0], cx[0], cx[1]); upk2(cv_[0][1], cx[2], cx[3]);
        upk2(cv_[1][0], cy[0], cy[1]); upk2(cv_[1][1], cy[2], cy[3]);
        upk2(cv_[2][0], cz[0], cz[1]); upk2(cv_[2][1], cz[2], cz[3]);
        #pragma unroll
        for (int j = 0; j < 4; j++) {
            int g = g0 + j;
            float4 sk = d_skip[n * 64 + g];
            float hso = cs[j]*INV + sk.x;
            float v0 = cx[j]*INV + sk.y;
            float v1 = cy[j]*INV + sk.z;
            float v2 = cz[j]*INV + sk.w;
            out[Nn + n * 64 + g] = hso;
            ohv[(n * 64 + g) * 3 + 0] = v0;
            ohv[(n * 64 + g) * 3 + 1] = v1;
            ohv[(n * 64 + g) * 3 + 2] = v2;
            partial += hso * sWr[g];
        }
    }
    partial += __shfl_down_sync(0xffffffffu, partial, 8, 16);
    partial += __shfl_down_sync(0xffffffffu, partial, 4, 16);
    partial += __shfl_down_sync(0xffffffffu, partial, 2, 16);
    partial += __shfl_down_sync(0xffffffffu, partial, 1, 16);
    if ((tid & 15) == 0 && valid) out[n] = partial * INV;
}

extern "C" void kernel_launch(void* const* d_in, const int* in_sizes, int n_in,
                              void* d_out, int out_size) {
    (void)in_sizes; (void)n_in; (void)out_size;
    const float* vectors   = (const float*)d_in[0];
    const float* node_s    = (const float*)d_in[1];
    const float* node_v    = (const float*)d_in[2];
    const float* radial    = (const float*)d_in[3];
    const int*   senders   = (const int*)d_in[4];
    const int*   receivers = (const int*)d_in[5];
    const int*   counts    = (const int*)d_in[6];
    const float* Wup0 = (const float*)d_in[7];
    const float* Wup1 = (const float*)d_in[8];
    const float* R1   = (const float*)d_in[9];
    const float* R2   = (const float*)d_in[10];
    const float* R3   = (const float*)d_in[11];
    const float* R4   = (const float*)d_in[12];
    const float* Wd0  = (const float*)d_in[13];
    const float* Wd1  = (const float*)d_in[14];
    const float* Ws0  = (const float*)d_in[15];
    const float* Ws1  = (const float*)d_in[16];
    const float* Wsc  = (const float*)d_in[17];
    const float* Proj = (const float*)d_in[18];
    const float* Wl0  = (const float*)d_in[19];
    const float* Wl1  = (const float*)d_in[20];
    const float* Wr   = (const float*)d_in[21];
    float* out = (float*)d_out;

    cudaFuncSetAttribute(kA, cudaFuncAttributeMaxDynamicSharedMemorySize, SMA_BYTES);
    cudaFuncSetAttribute(kB, cudaFuncAttributeMaxDynamicSharedMemorySize, SMB_BYTES);
    cudaFuncSetAttribute(kC, cudaFuncAttributeMaxDynamicSharedMemorySize, SMC_BYTES);

    void* accp = nullptr;
    cudaGetSymbolAddress(&accp, d_acc);
    cudaMemsetAsync(accp, 0, sizeof(float4) * Nn * Fc, 0);

    k0<<<1, 256>>>(counts, Wsc, Proj);
    kA<<<Nn / 25, 400, SMA_BYTES>>>(node_s, node_v, Wup0, Wup1, Ws0, Ws1);
    kB<<<304, 256, SMB_BYTES>>>(vectors, radial, senders, receivers, R1, R2, R3, R4);
    kC<<<(Nn + 31) / 32, 512, SMC_BYTES>>>(Wd0, Wd1, Wl0, Wl1, Wr, out);
}